// round 14
// baseline (speedup 1.0000x reference)
#include <cuda_runtime.h>
#include <cuda_bf16.h>
#include <cstdint>

#define NN    4096
#define IN_D  512
#define OUT_D 128
#define KNET  4
#define ALPHA 0.2f
#define NSPLIT 16
#define CH    (NN / 64 / NSPLIT)     // 4 chunks of 64 j per CTA

// fused-kernel smem layout (bytes) — R8 layout
#define EPITCH  72                   // E pitch (bf16 elems): 144B rows
#define WHPITCH 136                  // Wh pitch (bf16 elems): 272B rows
#define WH_TILE (64 * WHPITCH * 2)   // 17408
#define SM_EH 0
#define SM_EL 18432
#define SM_WH 36864                  // [2 buf][hi,lo] tiles
#define SM_W2 106496                 // 2 x 256 floats
#define SMEM_TOTAL 108544

// Scratch (device globals — no allocation allowed)
__device__ float g_Wh1[KNET * NN];
__device__ float g_Wh2[KNET * NN];
__device__ __nv_bfloat16 g_Wh_hi[NN * OUT_D];      // [token][c]
__device__ __nv_bfloat16 g_Wh_lo[NN * OUT_D];
__device__ uint32_t g_adjbits[(size_t)KNET * NN * NN / 32];   // 8 MB
__device__ float g_part[(size_t)NSPLIT * NN * OUT_D];         // 32 MB
__device__ float g_den[NSPLIT * NN];

// ============================ PTX helpers ============================
__device__ __forceinline__ uint32_t smem_u32(const void* p) {
    uint32_t a;
    asm("{ .reg .u64 t; cvta.to.shared.u64 t, %1; cvt.u32.u64 %0, t; }" : "=r"(a) : "l"(p));
    return a;
}
#define PACK_BF16X2(d, lo, hi) asm("cvt.rn.bf16x2.f32 %0, %1, %2;" : "=r"(d) : "f"(hi), "f"(lo))

__device__ __forceinline__ void ldsm_x4(uint32_t* r, uint32_t addr) {
    asm volatile("ldmatrix.sync.aligned.m8n8.x4.shared.b16 {%0,%1,%2,%3}, [%4];"
                 : "=r"(r[0]), "=r"(r[1]), "=r"(r[2]), "=r"(r[3]) : "r"(addr));
}
__device__ __forceinline__ void ldsm_x4_t(uint32_t* r, uint32_t addr) {
    asm volatile("ldmatrix.sync.aligned.m8n8.x4.trans.shared.b16 {%0,%1,%2,%3}, [%4];"
                 : "=r"(r[0]), "=r"(r[1]), "=r"(r[2]), "=r"(r[3]) : "r"(addr));
}
__device__ __forceinline__ void mma_bf16(float* d, const uint32_t* a, const uint32_t* b) {
    asm volatile(
        "mma.sync.aligned.m16n8k16.row.col.f32.bf16.bf16.f32 "
        "{%0,%1,%2,%3}, {%4,%5,%6,%7}, {%8,%9}, {%0,%1,%2,%3};"
        : "+f"(d[0]), "+f"(d[1]), "+f"(d[2]), "+f"(d[3])
        : "r"(a[0]), "r"(a[1]), "r"(a[2]), "r"(a[3]), "r"(b[0]), "r"(b[1]));
}

// FMA-pipe exp: exp2 magic-number range reduction + degree-6 poly.
// Valid for |x| < ~80; rel err ~1e-7.
__device__ __forceinline__ float fexp(float x) {
    const float MAGIC = 12582912.0f;              // 1.5 * 2^23
    float y = x * 1.4426950408889634f;
    float z = y + MAGIC;
    int   d = __float_as_int(z) - 0x4B400000;
    float f = y - (z - MAGIC);
    float p = 1.540353045101147e-4f;
    p = fmaf(p, f, 1.333355814670499e-3f);
    p = fmaf(p, f, 9.618129107628477e-3f);
    p = fmaf(p, f, 5.550410866482158e-2f);
    p = fmaf(p, f, 2.402265069591007e-1f);
    p = fmaf(p, f, 6.931471805599453e-1f);
    p = fmaf(p, f, 1.0f);
    return __int_as_float(__float_as_int(p) + (d << 23));
}

// ---------------------------------------------------------------------------
// Kernel 0: ballot bitpack (R8-proven: coalesced, no smem, high occupancy)
// ---------------------------------------------------------------------------
__global__ void __launch_bounds__(256) bitpack_kernel(const int* __restrict__ adjs)
{
    const int lane = threadIdx.x & 31;
    const size_t wg = ((size_t)blockIdx.x * 256 + threadIdx.x) >> 5;
    const size_t wb = wg * 128;
    const int* base = adjs + wb * 32 + lane;
    for (int it = 0; it < 16; it++) {
        int v[8];
        #pragma unroll
        for (int w = 0; w < 8; w++) v[w] = base[it * 256 + w * 32];
        uint32_t m[8];
        #pragma unroll
        for (int w = 0; w < 8; w++) m[w] = __ballot_sync(0xffffffffu, v[w] > 0);
        if (lane == 0) {
            uint4* dst = reinterpret_cast<uint4*>(&g_adjbits[wb + (size_t)it * 8]);
            dst[0] = make_uint4(m[0], m[1], m[2], m[3]);
            dst[1] = make_uint4(m[4], m[5], m[6], m[7]);
        }
    }
}

// ---------------------------------------------------------------------------
// Kernel 1: Wh GEMM + bf16 hi/lo split + Wh1/Wh2 projections (R12/R13-verified)
// ---------------------------------------------------------------------------
__global__ void __launch_bounds__(256) wh_prep_kernel(
    const float* __restrict__ h, const float* __restrict__ W,
    const float* __restrict__ a)
{
    __shared__ float hs[16][IN_D];    // 32 KB
    __shared__ float wt[16][132];     // padded row tile for proj dots
    const int t = threadIdx.x;
    const int row0 = blockIdx.x * 16;
    {
        const float4* src = reinterpret_cast<const float4*>(h + (size_t)row0 * IN_D);
        float4* dst = reinterpret_cast<float4*>(&hs[0][0]);
        #pragma unroll
        for (int i = 0; i < 8; i++) dst[t + i * 256] = src[t + i * 256];
    }
    __syncthreads();

    const int cg = t & 31, rg = t >> 5;
    const int i0 = rg * 2, c0 = cg * 4;
    const float4* Wp = reinterpret_cast<const float4*>(W) + cg;

    float4 wb4[8];
    #pragma unroll
    for (int i = 0; i < 8; i++) wb4[i] = Wp[i * 32];

    float acc[2][4] = {};
    for (int kb = 0; kb < IN_D; kb += 8) {
        float4 wn[8];
        const bool more = (kb + 8 < IN_D);
        #pragma unroll
        for (int i = 0; i < 8; i++)
            if (more) wn[i] = Wp[(kb + 8 + i) * 32];
        #pragma unroll
        for (int i = 0; i < 8; i++) {
            const float a0 = hs[i0][kb + i];
            const float a1 = hs[i0 + 1][kb + i];
            acc[0][0] = fmaf(a0, wb4[i].x, acc[0][0]);
            acc[0][1] = fmaf(a0, wb4[i].y, acc[0][1]);
            acc[0][2] = fmaf(a0, wb4[i].z, acc[0][2]);
            acc[0][3] = fmaf(a0, wb4[i].w, acc[0][3]);
            acc[1][0] = fmaf(a1, wb4[i].x, acc[1][0]);
            acc[1][1] = fmaf(a1, wb4[i].y, acc[1][1]);
            acc[1][2] = fmaf(a1, wb4[i].z, acc[1][2]);
            acc[1][3] = fmaf(a1, wb4[i].w, acc[1][3]);
        }
        #pragma unroll
        for (int i = 0; i < 8; i++) wb4[i] = wn[i];
    }

    // epilogue 1: bf16 hi/lo split direct from registers + smem stash
    #pragma unroll
    for (int rr = 0; rr < 2; rr++) {
        const int row = row0 + i0 + rr;
        __nv_bfloat16 hx = __float2bfloat16(acc[rr][0]), hy = __float2bfloat16(acc[rr][1]);
        __nv_bfloat16 hz = __float2bfloat16(acc[rr][2]), hw = __float2bfloat16(acc[rr][3]);
        __nv_bfloat162* H = reinterpret_cast<__nv_bfloat162*>(g_Wh_hi);
        __nv_bfloat162* L = reinterpret_cast<__nv_bfloat162*>(g_Wh_lo);
        const int hidx = row * (OUT_D / 2) + cg * 2;
        H[hidx + 0] = __nv_bfloat162(hx, hy);
        H[hidx + 1] = __nv_bfloat162(hz, hw);
        L[hidx + 0] = __nv_bfloat162(__float2bfloat16(acc[rr][0] - __bfloat162float(hx)),
                                     __float2bfloat16(acc[rr][1] - __bfloat162float(hy)));
        L[hidx + 1] = __nv_bfloat162(__float2bfloat16(acc[rr][2] - __bfloat162float(hz)),
                                     __float2bfloat16(acc[rr][3] - __bfloat162float(hw)));
        wt[i0 + rr][c0 + 0] = acc[rr][0];
        wt[i0 + rr][c0 + 1] = acc[rr][1];
        wt[i0 + rr][c0 + 2] = acc[rr][2];
        wt[i0 + rr][c0 + 3] = acc[rr][3];
    }
    __syncthreads();

    // epilogue 2: Wh1/Wh2 projections — 128 dots of length 128
    if (t < 128) {
        const int row = t >> 3;
        const int q   = t & 7;
        const float* av = a + q * 128;
        float p = 0.0f;
        #pragma unroll 16
        for (int i = 0; i < OUT_D; i++) p = fmaf(wt[row][i], av[i], p);
        const int k = q >> 1, d = q & 1;
        if (d == 0) g_Wh1[k * NN + row0 + row] = p;
        else        g_Wh2[k * NN + row0 + row] = p;
    }
}

// ---------------------------------------------------------------------------
// Kernel 2: fused  bits -> logits -> fexp -> bf16-split mma.sync -> partials
// R8/R13 structure (BM=128, 256 thr), NSPLIT=16 (grid 512 — fills occ-2 chip),
// next-chunk adjbits register prefetch hides the scattered LDG latency.
// ---------------------------------------------------------------------------
__global__ void __launch_bounds__(256, 2) attn_fused_kernel(const float* __restrict__ nw)
{
    extern __shared__ char smem[];
    const uint32_t sb = smem_u32(smem);
    float* w2s = reinterpret_cast<float*>(smem + SM_W2);

    const int t  = threadIdx.x;
    const int n0 = blockIdx.x * 128;
    const int s  = blockIdx.y;

    float wts[KNET];
    {
        float v0 = nw[0], v1 = nw[1], v2 = nw[2], v3 = nw[3];
        float mx = fmaxf(fmaxf(v0, v1), fmaxf(v2, v3));
        float e0 = fexp(v0 - mx), e1 = fexp(v1 - mx);
        float e2 = fexp(v2 - mx), e3 = fexp(v3 - mx);
        float inv = 1.0f / (e0 + e1 + e2 + e3);
        wts[0] = e0 * inv; wts[1] = e1 * inv; wts[2] = e2 * inv; wts[3] = e3 * inv;
    }

    const int r  = t >> 1;
    const int jh = t & 1;
    float w1k[KNET];
    #pragma unroll
    for (int k = 0; k < KNET; k++) w1k[k] = g_Wh1[k * NN + n0 + r];

    const int lane = t & 31;
    const int r0w  = (t >> 5) * 16;

    const int tokS = t >> 2;
    const int csS  = (t & 3) * 32;
    auto stage_wh = [&](int buf, int m0) {
        const uint4* srcH = reinterpret_cast<const uint4*>(
            g_Wh_hi + (size_t)(m0 + tokS) * OUT_D + csS);
        const uint4* srcL = reinterpret_cast<const uint4*>(
            g_Wh_lo + (size_t)(m0 + tokS) * OUT_D + csS);
        char* dstH = smem + SM_WH + buf * (2 * WH_TILE) + tokS * (WHPITCH * 2) + csS * 2;
        char* dstL = dstH + WH_TILE;
        #pragma unroll
        for (int i = 0; i < 4; i++) {
            reinterpret_cast<uint4*>(dstH)[i] = srcH[i];
            reinterpret_cast<uint4*>(dstL)[i] = srcL[i];
        }
    };
    auto stage_w2 = [&](int buf, int m0) {
        w2s[buf * 256 + t] = g_Wh2[(t >> 6) * NN + m0 + (t & 63)];
    };

    stage_wh(0, s * CH * 64);
    stage_w2(0, s * CH * 64);

    // prefetch chunk-0 adjacency words (4 scattered LDG, hidden behind staging)
    const size_t bitrow = ((size_t)(n0 + r) * NN) >> 5;
    const size_t kStrideW = (size_t)NN * NN / 32;
    uint32_t wk4[KNET];
    #pragma unroll
    for (int k = 0; k < KNET; k++)
        wk4[k] = g_adjbits[kStrideW * k + bitrow + (size_t)(s * CH * 2) + jh];

    __syncthreads();

    float acc[16][4];
    #pragma unroll
    for (int i = 0; i < 16; i++)
        #pragma unroll
        for (int q = 0; q < 4; q++) acc[i][q] = 0.0f;
    float denr = 0.0f;

    for (int ci = 0; ci < CH; ci++) {
        const int m0 = (s * CH + ci) * 64;
        const int buf = ci & 1;

        // L phase: logits -> E hi/lo (bits from the prefetched wk4)
        {
            uint32_t cur[KNET];
            #pragma unroll
            for (int k = 0; k < KNET; k++) cur[k] = wk4[k];
            if (ci + 1 < CH) {
                // prefetch next chunk's words; latency hides behind L compute
                #pragma unroll
                for (int k = 0; k < KNET; k++)
                    wk4[k] = g_adjbits[kStrideW * k + bitrow
                                       + (size_t)((s * CH + ci + 1) * 2) + jh];
            }

            const float* w2b = w2s + buf * 256 + jh * 32;

            #pragma unroll
            for (int h = 0; h < 2; h++) {
                float sv[16];
                #pragma unroll
                for (int i = 0; i < 16; i++) sv[i] = 0.0f;
                #pragma unroll
                for (int k = 0; k < KNET; k++) {
                    const float wkv = wts[k], b = w1k[k];
                    const uint32_t wd = cur[k] >> (h * 16);
                    #pragma unroll
                    for (int g = 0; g < 4; g++) {
                        const float4 w2v = *reinterpret_cast<const float4*>(
                            w2b + k * 64 + h * 16 + g * 4);
                        float v, lr;
                        v = b + w2v.x; lr = fmaxf(v, ALPHA * v);
                        sv[g*4+0] += (wd & (1u << (g*4+0))) ? wkv * lr : 0.0f;
                        v = b + w2v.y; lr = fmaxf(v, ALPHA * v);
                        sv[g*4+1] += (wd & (1u << (g*4+1))) ? wkv * lr : 0.0f;
                        v = b + w2v.z; lr = fmaxf(v, ALPHA * v);
                        sv[g*4+2] += (wd & (1u << (g*4+2))) ? wkv * lr : 0.0f;
                        v = b + w2v.w; lr = fmaxf(v, ALPHA * v);
                        sv[g*4+3] += (wd & (1u << (g*4+3))) ? wkv * lr : 0.0f;
                    }
                }
                const int jb = jh * 32 + h * 16;
                #pragma unroll
                for (int p = 0; p < 8; p++) {
                    float e0 = fexp(sv[2*p]), e1 = fexp(sv[2*p+1]);
                    denr += e0 + e1;
                    float h0 = __bfloat162float(__float2bfloat16(e0));
                    float h1 = __bfloat162float(__float2bfloat16(e1));
                    uint32_t hp, lp;
                    PACK_BF16X2(hp, e0, e1);
                    PACK_BF16X2(lp, e0 - h0, e1 - h1);
                    const int j = jb + 2 * p;
                    *reinterpret_cast<uint32_t*>(smem + SM_EH + r * (EPITCH*2) + j*2) = hp;
                    *reinterpret_cast<uint32_t*>(smem + SM_EL + r * (EPITCH*2) + j*2) = lp;
                }
            }
        }
        if (ci + 1 < CH) {
            stage_wh(buf ^ 1, m0 + 64);
            stage_w2(buf ^ 1, m0 + 64);
        }
        __syncthreads();

        // M phase: mma.sync
        {
            uint32_t Ah[4][4], Al[4][4];
            const uint32_t aoff = (uint32_t)(r0w + (lane & 15)) * (EPITCH*2)
                                + (uint32_t)(lane >> 4) * 16;
            #pragma unroll
            for (int kt = 0; kt < 4; kt++) {
                ldsm_x4(Ah[kt], sb + SM_EH + aoff + kt * 32);
                ldsm_x4(Al[kt], sb + SM_EL + aoff + kt * 32);
            }
            const uint32_t bbase = sb + SM_WH + buf * (2 * WH_TILE);
            const uint32_t boff = (uint32_t)(lane & 15) * (WHPITCH*2)
                                + (uint32_t)(lane >> 4) * 16;
            #pragma unroll
            for (int np = 0; np < 8; np++) {
                #pragma unroll
                for (int kt = 0; kt < 4; kt++) {
                    const uint32_t addr = bbase + boff + kt * (16 * WHPITCH * 2) + np * 32;
                    uint32_t Bh[4], Bl[4];
                    ldsm_x4_t(Bh, addr);
                    ldsm_x4_t(Bl, addr + WH_TILE);
                    float* a0 = acc[np * 2];
                    float* a1 = acc[np * 2 + 1];
                    mma_bf16(a0, Ah[kt], Bh);
                    mma_bf16(a0, Ah[kt], Bl);
                    mma_bf16(a0, Al[kt], Bh);
                    mma_bf16(a1, Ah[kt], Bh + 2);
                    mma_bf16(a1, Ah[kt], Bl + 2);
                    mma_bf16(a1, Al[kt], Bh + 2);
                }
            }
        }
        __syncthreads();
    }

    {
        const float dsum = denr + __shfl_xor_sync(0xffffffffu, denr, 1);
        if ((t & 1) == 0) g_den[s * NN + n0 + r] = dsum;
    }

    {
        const int rA = r0w + (lane >> 2);
        const int cA = (lane & 3) * 2;
        #pragma unroll
        for (int nt = 0; nt < 16; nt++) {
            const int col = nt * 8 + cA;
            float* base = &g_part[((size_t)s * NN + n0 + rA) * OUT_D + col];
            *reinterpret_cast<float2*>(base) = make_float2(acc[nt][0], acc[nt][1]);
            *reinterpret_cast<float2*>(base + 8 * OUT_D) = make_float2(acc[nt][2], acc[nt][3]);
        }
    }
}

// ---------------------------------------------------------------------------
// Kernel 3: combine NSPLIT partials, normalize, ELU, store
// ---------------------------------------------------------------------------
__global__ void __launch_bounds__(256) finalize_kernel(float* __restrict__ out)
{
    const int idx = blockIdx.x * 256 + threadIdx.x;
    const int n = idx >> 5;
    const float4* P = reinterpret_cast<const float4*>(g_part);
    float4 p = P[idx];
    float den = g_den[n];
    #pragma unroll
    for (int s = 1; s < NSPLIT; s++) {
        float4 q = P[idx + (size_t)s * (NN * OUT_D / 4)];
        p.x += q.x; p.y += q.y; p.z += q.z; p.w += q.w;
        den += g_den[s * NN + n];
    }
    const float inv = 1.0f / den;
    float4 o; float x;
    x = p.x * inv; o.x = x > 0.f ? x : fexp(x) - 1.0f;
    x = p.y * inv; o.y = x > 0.f ? x : fexp(x) - 1.0f;
    x = p.z * inv; o.z = x > 0.f ? x : fexp(x) - 1.0f;
    x = p.w * inv; o.w = x > 0.f ? x : fexp(x) - 1.0f;
    reinterpret_cast<float4*>(out)[idx] = o;
}

// ---------------------------------------------------------------------------
extern "C" void kernel_launch(void* const* d_in, const int* in_sizes, int n_in,
                              void* d_out, int out_size)
{
    const float* h    = (const float*)d_in[0];   // [4096, 512]
    const int*   adjs = (const int*)  d_in[1];   // [4, 4096, 4096]
    const float* W    = (const float*)d_in[2];   // [512, 128]
    const float* a    = (const float*)d_in[3];   // [1024]
    const float* nw   = (const float*)d_in[4];   // [4]
    float* out = (float*)d_out;                  // [4096, 128]

    cudaFuncSetAttribute(attn_fused_kernel,
                         cudaFuncAttributeMaxDynamicSharedMemorySize, SMEM_TOTAL);

    bitpack_kernel<<<2048, 256>>>(adjs);
    wh_prep_kernel<<<NN / 16, 256>>>(h, W, a);
    attn_fused_kernel<<<dim3(NN / 128, NSPLIT), 256, SMEM_TOTAL>>>(nw);
    finalize_kernel<<<NN * OUT_D / 4 / 256, 256>>>(out);
}

// round 15
// speedup vs baseline: 1.0791x; 1.0791x over previous
#include <cuda_runtime.h>
#include <cuda_bf16.h>
#include <cstdint>

#define NN    4096
#define IN_D  512
#define OUT_D 128
#define KNET  4
#define ALPHA 0.2f
#define NSPLIT 8
#define CH    (NN / 64 / NSPLIT)     // 8 chunks of 64 j per CTA

// fused-kernel smem layout (bytes) — R8/R13 layout
#define EPITCH  72                   // E pitch (bf16 elems): 144B rows
#define WHPITCH 136                  // Wh pitch (bf16 elems): 272B rows
#define WH_TILE (64 * WHPITCH * 2)   // 17408
#define SM_EH 0
#define SM_EL 18432
#define SM_WH 36864                  // [2 buf][hi,lo] tiles
#define SM_W2 106496                 // 2 x 256 floats
#define SMEM_TOTAL 108544

// Scratch (device globals — no allocation allowed)
__device__ float g_Wh1[KNET * NN];
__device__ float g_Wh2[KNET * NN];
__device__ __nv_bfloat16 g_Wh_hi[NN * OUT_D];      // [token][c]
__device__ __nv_bfloat16 g_Wh_lo[NN * OUT_D];
__device__ uint32_t g_adjbits[(size_t)KNET * NN * NN / 32];   // 8 MB
__device__ float g_part[(size_t)NSPLIT * NN * OUT_D];         // 16 MB
__device__ float g_den[NSPLIT * NN];

// ============================ PTX helpers ============================
__device__ __forceinline__ uint32_t smem_u32(const void* p) {
    uint32_t a;
    asm("{ .reg .u64 t; cvta.to.shared.u64 t, %1; cvt.u32.u64 %0, t; }" : "=r"(a) : "l"(p));
    return a;
}
#define PACK_BF16X2(d, lo, hi) asm("cvt.rn.bf16x2.f32 %0, %1, %2;" : "=r"(d) : "f"(hi), "f"(lo))

__device__ __forceinline__ void ldsm_x4(uint32_t* r, uint32_t addr) {
    asm volatile("ldmatrix.sync.aligned.m8n8.x4.shared.b16 {%0,%1,%2,%3}, [%4];"
                 : "=r"(r[0]), "=r"(r[1]), "=r"(r[2]), "=r"(r[3]) : "r"(addr));
}
__device__ __forceinline__ void ldsm_x4_t(uint32_t* r, uint32_t addr) {
    asm volatile("ldmatrix.sync.aligned.m8n8.x4.trans.shared.b16 {%0,%1,%2,%3}, [%4];"
                 : "=r"(r[0]), "=r"(r[1]), "=r"(r[2]), "=r"(r[3]) : "r"(addr));
}
__device__ __forceinline__ void mma_bf16(float* d, const uint32_t* a, const uint32_t* b) {
    asm volatile(
        "mma.sync.aligned.m16n8k16.row.col.f32.bf16.bf16.f32 "
        "{%0,%1,%2,%3}, {%4,%5,%6,%7}, {%8,%9}, {%0,%1,%2,%3};"
        : "+f"(d[0]), "+f"(d[1]), "+f"(d[2]), "+f"(d[3])
        : "r"(a[0]), "r"(a[1]), "r"(a[2]), "r"(a[3]), "r"(b[0]), "r"(b[1]));
}

// FMA-pipe exp: exp2 magic-number range reduction + degree-6 poly.
// Valid for |x| < ~80; rel err ~1e-7.
__device__ __forceinline__ float fexp(float x) {
    const float MAGIC = 12582912.0f;              // 1.5 * 2^23
    float y = x * 1.4426950408889634f;
    float z = y + MAGIC;
    int   d = __float_as_int(z) - 0x4B400000;
    float f = y - (z - MAGIC);
    float p = 1.540353045101147e-4f;
    p = fmaf(p, f, 1.333355814670499e-3f);
    p = fmaf(p, f, 9.618129107628477e-3f);
    p = fmaf(p, f, 5.550410866482158e-2f);
    p = fmaf(p, f, 2.402265069591007e-1f);
    p = fmaf(p, f, 6.931471805599453e-1f);
    p = fmaf(p, f, 1.0f);
    return __int_as_float(__float_as_int(p) + (d << 23));
}

// ---------------------------------------------------------------------------
// Kernel 0: ballot bitpack (R8-proven: coalesced, no smem, high occupancy)
// ---------------------------------------------------------------------------
__global__ void __launch_bounds__(256) bitpack_kernel(const int* __restrict__ adjs)
{
    const int lane = threadIdx.x & 31;
    const size_t wg = ((size_t)blockIdx.x * 256 + threadIdx.x) >> 5;
    const size_t wb = wg * 128;
    const int* base = adjs + wb * 32 + lane;
    for (int it = 0; it < 16; it++) {
        int v[8];
        #pragma unroll
        for (int w = 0; w < 8; w++) v[w] = base[it * 256 + w * 32];
        uint32_t m[8];
        #pragma unroll
        for (int w = 0; w < 8; w++) m[w] = __ballot_sync(0xffffffffu, v[w] > 0);
        if (lane == 0) {
            uint4* dst = reinterpret_cast<uint4*>(&g_adjbits[wb + (size_t)it * 8]);
            dst[0] = make_uint4(m[0], m[1], m[2], m[3]);
            dst[1] = make_uint4(m[4], m[5], m[6], m[7]);
        }
    }
}

// ---------------------------------------------------------------------------
// Kernel 1: Wh GEMM + bf16 hi/lo split + Wh1/Wh2 projections (R13-verified)
// ---------------------------------------------------------------------------
__global__ void __launch_bounds__(256) wh_prep_kernel(
    const float* __restrict__ h, const float* __restrict__ W,
    const float* __restrict__ a)
{
    __shared__ float hs[16][IN_D];    // 32 KB
    __shared__ float wt[16][132];     // padded row tile for proj dots
    const int t = threadIdx.x;
    const int row0 = blockIdx.x * 16;
    {
        const float4* src = reinterpret_cast<const float4*>(h + (size_t)row0 * IN_D);
        float4* dst = reinterpret_cast<float4*>(&hs[0][0]);
        #pragma unroll
        for (int i = 0; i < 8; i++) dst[t + i * 256] = src[t + i * 256];
    }
    __syncthreads();

    const int cg = t & 31, rg = t >> 5;
    const int i0 = rg * 2, c0 = cg * 4;
    const float4* Wp = reinterpret_cast<const float4*>(W) + cg;

    float4 wb4[8];
    #pragma unroll
    for (int i = 0; i < 8; i++) wb4[i] = Wp[i * 32];

    float acc[2][4] = {};
    for (int kb = 0; kb < IN_D; kb += 8) {
        float4 wn[8];
        const bool more = (kb + 8 < IN_D);
        #pragma unroll
        for (int i = 0; i < 8; i++)
            if (more) wn[i] = Wp[(kb + 8 + i) * 32];
        #pragma unroll
        for (int i = 0; i < 8; i++) {
            const float a0 = hs[i0][kb + i];
            const float a1 = hs[i0 + 1][kb + i];
            acc[0][0] = fmaf(a0, wb4[i].x, acc[0][0]);
            acc[0][1] = fmaf(a0, wb4[i].y, acc[0][1]);
            acc[0][2] = fmaf(a0, wb4[i].z, acc[0][2]);
            acc[0][3] = fmaf(a0, wb4[i].w, acc[0][3]);
            acc[1][0] = fmaf(a1, wb4[i].x, acc[1][0]);
            acc[1][1] = fmaf(a1, wb4[i].y, acc[1][1]);
            acc[1][2] = fmaf(a1, wb4[i].z, acc[1][2]);
            acc[1][3] = fmaf(a1, wb4[i].w, acc[1][3]);
        }
        #pragma unroll
        for (int i = 0; i < 8; i++) wb4[i] = wn[i];
    }

    // epilogue 1: bf16 hi/lo split direct from registers + smem stash
    #pragma unroll
    for (int rr = 0; rr < 2; rr++) {
        const int row = row0 + i0 + rr;
        __nv_bfloat16 hx = __float2bfloat16(acc[rr][0]), hy = __float2bfloat16(acc[rr][1]);
        __nv_bfloat16 hz = __float2bfloat16(acc[rr][2]), hw = __float2bfloat16(acc[rr][3]);
        __nv_bfloat162* H = reinterpret_cast<__nv_bfloat162*>(g_Wh_hi);
        __nv_bfloat162* L = reinterpret_cast<__nv_bfloat162*>(g_Wh_lo);
        const int hidx = row * (OUT_D / 2) + cg * 2;
        H[hidx + 0] = __nv_bfloat162(hx, hy);
        H[hidx + 1] = __nv_bfloat162(hz, hw);
        L[hidx + 0] = __nv_bfloat162(__float2bfloat16(acc[rr][0] - __bfloat162float(hx)),
                                     __float2bfloat16(acc[rr][1] - __bfloat162float(hy)));
        L[hidx + 1] = __nv_bfloat162(__float2bfloat16(acc[rr][2] - __bfloat162float(hz)),
                                     __float2bfloat16(acc[rr][3] - __bfloat162float(hw)));
        wt[i0 + rr][c0 + 0] = acc[rr][0];
        wt[i0 + rr][c0 + 1] = acc[rr][1];
        wt[i0 + rr][c0 + 2] = acc[rr][2];
        wt[i0 + rr][c0 + 3] = acc[rr][3];
    }
    __syncthreads();

    // epilogue 2: Wh1/Wh2 projections — 128 dots of length 128
    if (t < 128) {
        const int row = t >> 3;
        const int q   = t & 7;
        const float* av = a + q * 128;
        float p = 0.0f;
        #pragma unroll 16
        for (int i = 0; i < OUT_D; i++) p = fmaf(wt[row][i], av[i], p);
        const int k = q >> 1, d = q & 1;
        if (d == 0) g_Wh1[k * NN + row0 + row] = p;
        else        g_Wh2[k * NN + row0 + row] = p;
    }
}

// ---------------------------------------------------------------------------
// Kernel 2: fused  bits -> logits -> fexp -> bf16-split mma.sync -> partials
// EXACT R13 structure (BM=128, 256 thr, NSPLIT=8 — measured best).
// ---------------------------------------------------------------------------
__global__ void __launch_bounds__(256, 2) attn_fused_kernel(const float* __restrict__ nw)
{
    extern __shared__ char smem[];
    const uint32_t sb = smem_u32(smem);
    float* w2s = reinterpret_cast<float*>(smem + SM_W2);

    const int t  = threadIdx.x;
    const int n0 = blockIdx.x * 128;
    const int s  = blockIdx.y;

    float wts[KNET];
    {
        float v0 = nw[0], v1 = nw[1], v2 = nw[2], v3 = nw[3];
        float mx = fmaxf(fmaxf(v0, v1), fmaxf(v2, v3));
        float e0 = fexp(v0 - mx), e1 = fexp(v1 - mx);
        float e2 = fexp(v2 - mx), e3 = fexp(v3 - mx);
        float inv = 1.0f / (e0 + e1 + e2 + e3);
        wts[0] = e0 * inv; wts[1] = e1 * inv; wts[2] = e2 * inv; wts[3] = e3 * inv;
    }

    const int r  = t >> 1;
    const int jh = t & 1;
    float w1k[KNET];
    #pragma unroll
    for (int k = 0; k < KNET; k++) w1k[k] = g_Wh1[k * NN + n0 + r];

    const int lane = t & 31;
    const int r0w  = (t >> 5) * 16;

    const int tokS = t >> 2;
    const int csS  = (t & 3) * 32;
    auto stage_wh = [&](int buf, int m0) {
        const uint4* srcH = reinterpret_cast<const uint4*>(
            g_Wh_hi + (size_t)(m0 + tokS) * OUT_D + csS);
        const uint4* srcL = reinterpret_cast<const uint4*>(
            g_Wh_lo + (size_t)(m0 + tokS) * OUT_D + csS);
        char* dstH = smem + SM_WH + buf * (2 * WH_TILE) + tokS * (WHPITCH * 2) + csS * 2;
        char* dstL = dstH + WH_TILE;
        #pragma unroll
        for (int i = 0; i < 4; i++) {
            reinterpret_cast<uint4*>(dstH)[i] = srcH[i];
            reinterpret_cast<uint4*>(dstL)[i] = srcL[i];
        }
    };
    auto stage_w2 = [&](int buf, int m0) {
        w2s[buf * 256 + t] = g_Wh2[(t >> 6) * NN + m0 + (t & 63)];
    };

    stage_wh(0, s * CH * 64);
    stage_w2(0, s * CH * 64);
    __syncthreads();

    float acc[16][4];
    #pragma unroll
    for (int i = 0; i < 16; i++)
        #pragma unroll
        for (int q = 0; q < 4; q++) acc[i][q] = 0.0f;
    float denr = 0.0f;

    for (int ci = 0; ci < CH; ci++) {
        const int m0 = (s * CH + ci) * 64;
        const int buf = ci & 1;

        // L phase: logits -> E hi/lo
        {
            const size_t bitbase = (((size_t)(n0 + r) * NN + m0) >> 5) + jh;
            uint32_t wk4[KNET];
            #pragma unroll
            for (int k = 0; k < KNET; k++)
                wk4[k] = g_adjbits[(size_t)k * ((size_t)NN * NN / 32) + bitbase];

            const float* w2b = w2s + buf * 256 + jh * 32;

            #pragma unroll
            for (int h = 0; h < 2; h++) {
                float sv[16];
                #pragma unroll
                for (int i = 0; i < 16; i++) sv[i] = 0.0f;
                #pragma unroll
                for (int k = 0; k < KNET; k++) {
                    const float wkv = wts[k], b = w1k[k];
                    const uint32_t wd = wk4[k] >> (h * 16);
                    #pragma unroll
                    for (int g = 0; g < 4; g++) {
                        const float4 w2v = *reinterpret_cast<const float4*>(
                            w2b + k * 64 + h * 16 + g * 4);
                        float v, lr;
                        v = b + w2v.x; lr = fmaxf(v, ALPHA * v);
                        sv[g*4+0] += (wd & (1u << (g*4+0))) ? wkv * lr : 0.0f;
                        v = b + w2v.y; lr = fmaxf(v, ALPHA * v);
                        sv[g*4+1] += (wd & (1u << (g*4+1))) ? wkv * lr : 0.0f;
                        v = b + w2v.z; lr = fmaxf(v, ALPHA * v);
                        sv[g*4+2] += (wd & (1u << (g*4+2))) ? wkv * lr : 0.0f;
                        v = b + w2v.w; lr = fmaxf(v, ALPHA * v);
                        sv[g*4+3] += (wd & (1u << (g*4+3))) ? wkv * lr : 0.0f;
                    }
                }
                const int jb = jh * 32 + h * 16;
                #pragma unroll
                for (int p = 0; p < 8; p++) {
                    float e0 = fexp(sv[2*p]), e1 = fexp(sv[2*p+1]);
                    denr += e0 + e1;
                    float h0 = __bfloat162float(__float2bfloat16(e0));
                    float h1 = __bfloat162float(__float2bfloat16(e1));
                    uint32_t hp, lp;
                    PACK_BF16X2(hp, e0, e1);
                    PACK_BF16X2(lp, e0 - h0, e1 - h1);
                    const int j = jb + 2 * p;
                    *reinterpret_cast<uint32_t*>(smem + SM_EH + r * (EPITCH*2) + j*2) = hp;
                    *reinterpret_cast<uint32_t*>(smem + SM_EL + r * (EPITCH*2) + j*2) = lp;
                }
            }
        }
        if (ci + 1 < CH) {
            stage_wh(buf ^ 1, m0 + 64);
            stage_w2(buf ^ 1, m0 + 64);
        }
        __syncthreads();

        // M phase: mma.sync
        {
            uint32_t Ah[4][4], Al[4][4];
            const uint32_t aoff = (uint32_t)(r0w + (lane & 15)) * (EPITCH*2)
                                + (uint32_t)(lane >> 4) * 16;
            #pragma unroll
            for (int kt = 0; kt < 4; kt++) {
                ldsm_x4(Ah[kt], sb + SM_EH + aoff + kt * 32);
                ldsm_x4(Al[kt], sb + SM_EL + aoff + kt * 32);
            }
            const uint32_t bbase = sb + SM_WH + buf * (2 * WH_TILE);
            const uint32_t boff = (uint32_t)(lane & 15) * (WHPITCH*2)
                                + (uint32_t)(lane >> 4) * 16;
            #pragma unroll
            for (int np = 0; np < 8; np++) {
                #pragma unroll
                for (int kt = 0; kt < 4; kt++) {
                    const uint32_t addr = bbase + boff + kt * (16 * WHPITCH * 2) + np * 32;
                    uint32_t Bh[4], Bl[4];
                    ldsm_x4_t(Bh, addr);
                    ldsm_x4_t(Bl, addr + WH_TILE);
                    float* a0 = acc[np * 2];
                    float* a1 = acc[np * 2 + 1];
                    mma_bf16(a0, Ah[kt], Bh);
                    mma_bf16(a0, Ah[kt], Bl);
                    mma_bf16(a0, Al[kt], Bh);
                    mma_bf16(a1, Ah[kt], Bh + 2);
                    mma_bf16(a1, Ah[kt], Bl + 2);
                    mma_bf16(a1, Al[kt], Bh + 2);
                }
            }
        }
        __syncthreads();
    }

    {
        const float dsum = denr + __shfl_xor_sync(0xffffffffu, denr, 1);
        if ((t & 1) == 0) g_den[s * NN + n0 + r] = dsum;
    }

    {
        const int rA = r0w + (lane >> 2);
        const int cA = (lane & 3) * 2;
        #pragma unroll
        for (int nt = 0; nt < 16; nt++) {
            const int col = nt * 8 + cA;
            float* base = &g_part[((size_t)s * NN + n0 + rA) * OUT_D + col];
            *reinterpret_cast<float2*>(base) = make_float2(acc[nt][0], acc[nt][1]);
            *reinterpret_cast<float2*>(base + 8 * OUT_D) = make_float2(acc[nt][2], acc[nt][3]);
        }
    }
}

// ---------------------------------------------------------------------------
// Kernel 3: combine NSPLIT partials, normalize, ELU, store
// ---------------------------------------------------------------------------
__global__ void __launch_bounds__(256) finalize_kernel(float* __restrict__ out)
{
    const int idx = blockIdx.x * 256 + threadIdx.x;
    const int n = idx >> 5;
    const float4* P = reinterpret_cast<const float4*>(g_part);
    float4 p = P[idx];
    float den = g_den[n];
    #pragma unroll
    for (int s = 1; s < NSPLIT; s++) {
        float4 q = P[idx + (size_t)s * (NN * OUT_D / 4)];
        p.x += q.x; p.y += q.y; p.z += q.z; p.w += q.w;
        den += g_den[s * NN + n];
    }
    const float inv = 1.0f / den;
    float4 o; float x;
    x = p.x * inv; o.x = x > 0.f ? x : fexp(x) - 1.0f;
    x = p.y * inv; o.y = x > 0.f ? x : fexp(x) - 1.0f;
    x = p.z * inv; o.z = x > 0.f ? x : fexp(x) - 1.0f;
    x = p.w * inv; o.w = x > 0.f ? x : fexp(x) - 1.0f;
    reinterpret_cast<float4*>(out)[idx] = o;
}

// ---------------------------------------------------------------------------
// Stream fork infrastructure: created once at static-init time (host-side
// objects; no device allocation in kernel_launch). kernel_launch performs
// the same record/wait/launch sequence on every call (deterministic work).
// Fallback to serial launches if creation failed.
// ---------------------------------------------------------------------------
namespace {
struct AuxStream {
    cudaStream_t s = nullptr;
    cudaEvent_t  e0 = nullptr, e1 = nullptr;
    bool ok = false;
    AuxStream() {
        ok = (cudaStreamCreateWithFlags(&s, cudaStreamNonBlocking) == cudaSuccess)
          && (cudaEventCreateWithFlags(&e0, cudaEventDisableTiming) == cudaSuccess)
          && (cudaEventCreateWithFlags(&e1, cudaEventDisableTiming) == cudaSuccess);
    }
};
AuxStream g_aux;
}

// ---------------------------------------------------------------------------
extern "C" void kernel_launch(void* const* d_in, const int* in_sizes, int n_in,
                              void* d_out, int out_size)
{
    const float* h    = (const float*)d_in[0];   // [4096, 512]
    const int*   adjs = (const int*)  d_in[1];   // [4, 4096, 4096]
    const float* W    = (const float*)d_in[2];   // [512, 128]
    const float* a    = (const float*)d_in[3];   // [1024]
    const float* nw   = (const float*)d_in[4];   // [4]
    float* out = (float*)d_out;                  // [4096, 128]

    cudaFuncSetAttribute(attn_fused_kernel,
                         cudaFuncAttributeMaxDynamicSharedMemorySize, SMEM_TOTAL);

    if (g_aux.ok) {
        // fork: bitpack (DRAM-bound) runs concurrently with wh_prep (FFMA-bound)
        cudaEventRecord(g_aux.e0, 0);
        cudaStreamWaitEvent(g_aux.s, g_aux.e0, 0);
        bitpack_kernel<<<2048, 256, 0, g_aux.s>>>(adjs);
        cudaEventRecord(g_aux.e1, g_aux.s);
        wh_prep_kernel<<<NN / 16, 256>>>(h, W, a);
        cudaStreamWaitEvent(0, g_aux.e1, 0);    // join before fused
    } else {
        bitpack_kernel<<<2048, 256>>>(adjs);
        wh_prep_kernel<<<NN / 16, 256>>>(h, W, a);
    }
    attn_fused_kernel<<<dim3(NN / 128, NSPLIT), 256, SMEM_TOTAL>>>(nw);
    finalize_kernel<<<NN * OUT_D / 4 / 256, 256>>>(out);
}

// round 16
// speedup vs baseline: 1.2809x; 1.1870x over previous
#include <cuda_runtime.h>
#include <cuda_bf16.h>
#include <cstdint>

#define NN    4096
#define IN_D  512
#define OUT_D 128
#define KNET  4
#define ALPHA 0.2f
#define NSPLIT 8
#define CH    (NN / 64 / NSPLIT)     // 8 chunks of 64 j per CTA

// fused-kernel smem layout (bytes)
#define WHPITCH 136                  // Wh pitch (bf16 elems): 272B rows
#define WH_TILE (64 * WHPITCH * 2)   // 17408
#define SM_WH 0                      // [2 buf][hi,lo] tiles = 69632
#define SM_W2 69632                  // 2 x 256 floats = 2048
#define SM_MK 71680                  // 2 x 1024 uint32 mask words = 8192
#define SMEM_TOTAL 79872

// Scratch (device globals — no allocation allowed)
__device__ float g_Wh1[KNET * NN];
__device__ float g_Wh2[KNET * NN];
__device__ __nv_bfloat16 g_Wh_hi[NN * OUT_D];      // [token][c]
__device__ __nv_bfloat16 g_Wh_lo[NN * OUT_D];
// transposed bit layout: word[k][jw][n],  addr = k*524288 + jw*4096 + n
__device__ uint32_t g_adjbits[(size_t)KNET * NN * NN / 32];   // 8 MB
__device__ float g_part[(size_t)NSPLIT * NN * OUT_D];         // 16 MB
__device__ float g_den[NSPLIT * NN];

// ============================ PTX helpers ============================
__device__ __forceinline__ uint32_t smem_u32(const void* p) {
    uint32_t a;
    asm("{ .reg .u64 t; cvta.to.shared.u64 t, %1; cvt.u32.u64 %0, t; }" : "=r"(a) : "l"(p));
    return a;
}
#define PACK_BF16X2(d, lo, hi) asm("cvt.rn.bf16x2.f32 %0, %1, %2;" : "=r"(d) : "f"(hi), "f"(lo))

__device__ __forceinline__ void ldsm_x4_t(uint32_t* r, uint32_t addr) {
    asm volatile("ldmatrix.sync.aligned.m8n8.x4.trans.shared.b16 {%0,%1,%2,%3}, [%4];"
                 : "=r"(r[0]), "=r"(r[1]), "=r"(r[2]), "=r"(r[3]) : "r"(addr));
}
__device__ __forceinline__ void mma_bf16(float* d, const uint32_t* a, const uint32_t* b) {
    asm volatile(
        "mma.sync.aligned.m16n8k16.row.col.f32.bf16.bf16.f32 "
        "{%0,%1,%2,%3}, {%4,%5,%6,%7}, {%8,%9}, {%0,%1,%2,%3};"
        : "+f"(d[0]), "+f"(d[1]), "+f"(d[2]), "+f"(d[3])
        : "r"(a[0]), "r"(a[1]), "r"(a[2]), "r"(a[3]), "r"(b[0]), "r"(b[1]));
}

// FMA-pipe exp (exp2 magic-number reduction + degree-6 poly, rel err ~1e-7)
__device__ __forceinline__ float fexp(float x) {
    const float MAGIC = 12582912.0f;              // 1.5 * 2^23
    float y = x * 1.4426950408889634f;
    float z = y + MAGIC;
    int   d = __float_as_int(z) - 0x4B400000;
    float f = y - (z - MAGIC);
    float p = 1.540353045101147e-4f;
    p = fmaf(p, f, 1.333355814670499e-3f);
    p = fmaf(p, f, 9.618129107628477e-3f);
    p = fmaf(p, f, 5.550410866482158e-2f);
    p = fmaf(p, f, 2.402265069591007e-1f);
    p = fmaf(p, f, 6.931471805599453e-1f);
    p = fmaf(p, f, 1.0f);
    return __int_as_float(__float_as_int(p) + (d << 23));
}

// ---------------------------------------------------------------------------
// Kernel 0: ballot bitpack into TRANSPOSED layout word[k][jw][n].
// Reads: fully coalesced (ballot pattern, R8-proven).
// Writes: smem transpose -> 32B-sector-perfect stores.
// CTA covers 1024 flat words = 8 consecutive n rows (one k).
// ---------------------------------------------------------------------------
__global__ void __launch_bounds__(256) bitpack_kernel(const int* __restrict__ adjs)
{
    __shared__ uint32_t trans[128][8];   // [jw][n8]
    const int t = threadIdx.x;
    const int lane = t & 31;
    const int wci = t >> 5;                       // warp in CTA: 0..7
    const size_t base = (size_t)blockIdx.x * 1024;  // flat word base
    const size_t wb = base + (size_t)wci * 128;   // this warp's 128 words
    const int* src = adjs + wb * 32 + lane;

    for (int it = 0; it < 16; it++) {
        int v[8];
        #pragma unroll
        for (int w = 0; w < 8; w++) v[w] = src[it * 256 + w * 32];
        #pragma unroll
        for (int w = 0; w < 8; w++) {
            const uint32_t m = __ballot_sync(0xffffffffu, v[w] > 0);
            if (lane == 0) trans[it * 8 + w][wci] = m;
        }
    }
    __syncthreads();

    // write out: dst = k*524288 + jw*4096 + nbase + n8, uint4 over n8
    const size_t kpart = base & ~(size_t)524287;
    const int nbase = (int)((base & 524287) >> 7);   // multiple of 8
    const int jw = t >> 1;
    const int q  = (t & 1) * 4;
    uint4 o = make_uint4(trans[jw][q], trans[jw][q + 1], trans[jw][q + 2], trans[jw][q + 3]);
    *reinterpret_cast<uint4*>(&g_adjbits[kpart + (size_t)jw * NN + nbase + q]) = o;
}

// ---------------------------------------------------------------------------
// Kernel 1: Wh GEMM + bf16 hi/lo split + Wh1/Wh2 projections (R13-verified)
// ---------------------------------------------------------------------------
__global__ void __launch_bounds__(256) wh_prep_kernel(
    const float* __restrict__ h, const float* __restrict__ W,
    const float* __restrict__ a)
{
    __shared__ float hs[16][IN_D];    // 32 KB
    __shared__ float wt[16][132];
    const int t = threadIdx.x;
    const int row0 = blockIdx.x * 16;
    {
        const float4* src = reinterpret_cast<const float4*>(h + (size_t)row0 * IN_D);
        float4* dst = reinterpret_cast<float4*>(&hs[0][0]);
        #pragma unroll
        for (int i = 0; i < 8; i++) dst[t + i * 256] = src[t + i * 256];
    }
    __syncthreads();

    const int cg = t & 31, rg = t >> 5;
    const int i0 = rg * 2, c0 = cg * 4;
    const float4* Wp = reinterpret_cast<const float4*>(W) + cg;

    float4 wb4[8];
    #pragma unroll
    for (int i = 0; i < 8; i++) wb4[i] = Wp[i * 32];

    float acc[2][4] = {};
    for (int kb = 0; kb < IN_D; kb += 8) {
        float4 wn[8];
        const bool more = (kb + 8 < IN_D);
        #pragma unroll
        for (int i = 0; i < 8; i++)
            if (more) wn[i] = Wp[(kb + 8 + i) * 32];
        #pragma unroll
        for (int i = 0; i < 8; i++) {
            const float a0 = hs[i0][kb + i];
            const float a1 = hs[i0 + 1][kb + i];
            acc[0][0] = fmaf(a0, wb4[i].x, acc[0][0]);
            acc[0][1] = fmaf(a0, wb4[i].y, acc[0][1]);
            acc[0][2] = fmaf(a0, wb4[i].z, acc[0][2]);
            acc[0][3] = fmaf(a0, wb4[i].w, acc[0][3]);
            acc[1][0] = fmaf(a1, wb4[i].x, acc[1][0]);
            acc[1][1] = fmaf(a1, wb4[i].y, acc[1][1]);
            acc[1][2] = fmaf(a1, wb4[i].z, acc[1][2]);
            acc[1][3] = fmaf(a1, wb4[i].w, acc[1][3]);
        }
        #pragma unroll
        for (int i = 0; i < 8; i++) wb4[i] = wn[i];
    }

    #pragma unroll
    for (int rr = 0; rr < 2; rr++) {
        const int row = row0 + i0 + rr;
        __nv_bfloat16 hx = __float2bfloat16(acc[rr][0]), hy = __float2bfloat16(acc[rr][1]);
        __nv_bfloat16 hz = __float2bfloat16(acc[rr][2]), hw = __float2bfloat16(acc[rr][3]);
        __nv_bfloat162* H = reinterpret_cast<__nv_bfloat162*>(g_Wh_hi);
        __nv_bfloat162* L = reinterpret_cast<__nv_bfloat162*>(g_Wh_lo);
        const int hidx = row * (OUT_D / 2) + cg * 2;
        H[hidx + 0] = __nv_bfloat162(hx, hy);
        H[hidx + 1] = __nv_bfloat162(hz, hw);
        L[hidx + 0] = __nv_bfloat162(__float2bfloat16(acc[rr][0] - __bfloat162float(hx)),
                                     __float2bfloat16(acc[rr][1] - __bfloat162float(hy)));
        L[hidx + 1] = __nv_bfloat162(__float2bfloat16(acc[rr][2] - __bfloat162float(hz)),
                                     __float2bfloat16(acc[rr][3] - __bfloat162float(hw)));
        wt[i0 + rr][c0 + 0] = acc[rr][0];
        wt[i0 + rr][c0 + 1] = acc[rr][1];
        wt[i0 + rr][c0 + 2] = acc[rr][2];
        wt[i0 + rr][c0 + 3] = acc[rr][3];
    }
    __syncthreads();

    if (t < 128) {
        const int row = t >> 3;
        const int q   = t & 7;
        const float* av = a + q * 128;
        float p = 0.0f;
        #pragma unroll 16
        for (int i = 0; i < OUT_D; i++) p = fmaf(wt[row][i], av[i], p);
        const int k = q >> 1, d = q & 1;
        if (d == 0) g_Wh1[k * NN + row0 + row] = p;
        else        g_Wh2[k * NN + row0 + row] = p;
    }
}

// ---------------------------------------------------------------------------
// Kernel 2: fused logits -> fexp -> bf16-split mma.sync, A-fragments built
// DIRECTLY in registers (E is warp-exclusive; no E smem, 1 barrier/chunk).
// Thread lane computes rows r0w+lane/4, +8 at K-cols (lane%4)*2+{0,1,8,9}
// per 16-wide k-tile — exactly the m16n8k16 A fragment layout.
// ---------------------------------------------------------------------------
__global__ void __launch_bounds__(256, 2) attn_fused_kernel(const float* __restrict__ nw)
{
    extern __shared__ char smem[];
    const uint32_t sb = smem_u32(smem);
    float*    w2s = reinterpret_cast<float*>(smem + SM_W2);
    uint32_t* mks = reinterpret_cast<uint32_t*>(smem + SM_MK);

    const int t  = threadIdx.x;
    const int lane = t & 31;
    const int wrp  = t >> 5;
    const int r0w  = wrp * 16;
    const int n0 = blockIdx.x * 128;
    const int s  = blockIdx.y;

    float wts[KNET];
    {
        float v0 = nw[0], v1 = nw[1], v2 = nw[2], v3 = nw[3];
        float mx = fmaxf(fmaxf(v0, v1), fmaxf(v2, v3));
        float e0 = fexp(v0 - mx), e1 = fexp(v1 - mx);
        float e2 = fexp(v2 - mx), e3 = fexp(v3 - mx);
        float inv = 1.0f / (e0 + e1 + e2 + e3);
        wts[0] = e0 * inv; wts[1] = e1 * inv; wts[2] = e2 * inv; wts[3] = e3 * inv;
    }

    const int lane4 = lane >> 2;          // 0..7
    const int rowA  = r0w + lane4;        // block-relative rows this thread owns
    const int rowB  = rowA + 8;
    const int c0j   = (lane & 3) * 2;

    float w1A[KNET], w1B[KNET];
    #pragma unroll
    for (int k = 0; k < KNET; k++) {
        w1A[k] = g_Wh1[k * NN + n0 + rowA];
        w1B[k] = g_Wh1[k * NN + n0 + rowB];
    }

    // staging helpers
    const int tokS = t >> 2;
    const int csS  = (t & 3) * 32;
    auto stage_wh = [&](int buf, int m0) {
        const uint4* srcH = reinterpret_cast<const uint4*>(
            g_Wh_hi + (size_t)(m0 + tokS) * OUT_D + csS);
        const uint4* srcL = reinterpret_cast<const uint4*>(
            g_Wh_lo + (size_t)(m0 + tokS) * OUT_D + csS);
        char* dstH = smem + SM_WH + buf * (2 * WH_TILE) + tokS * (WHPITCH * 2) + csS * 2;
        char* dstL = dstH + WH_TILE;
        #pragma unroll
        for (int i = 0; i < 4; i++) {
            reinterpret_cast<uint4*>(dstH)[i] = srcH[i];
            reinterpret_cast<uint4*>(dstL)[i] = srcL[i];
        }
    };
    auto stage_w2 = [&](int buf, int m0) {
        w2s[buf * 256 + t] = g_Wh2[(t >> 6) * NN + m0 + (t & 63)];
    };
    // transposed adjbits: word[k][jw][n] = g_adjbits[k*524288 + jw*4096 + n]
    auto stage_mk = [&](int buf, int m0) {
        const int jw0 = m0 >> 5;
        #pragma unroll
        for (int i = 0; i < 4; i++) {
            const int idx = t + i * 256;          // 0..1023
            const int g = idx >> 7;               // k = g>>1, wsel = g&1
            const int n = idx & 127;
            mks[buf * 1024 + g * 128 + n] =
                g_adjbits[(size_t)(g >> 1) * ((size_t)NN * NN / 32)
                          + (size_t)(jw0 + (g & 1)) * NN + n0 + n];
        }
    };

    const int m0base = s * CH * 64;
    stage_wh(0, m0base);
    stage_w2(0, m0base);
    stage_mk(0, m0base);
    __syncthreads();

    float acc[16][4];
    #pragma unroll
    for (int i = 0; i < 16; i++)
        #pragma unroll
        for (int q = 0; q < 4; q++) acc[i][q] = 0.0f;
    float denA = 0.0f, denB = 0.0f;

    for (int ci = 0; ci < CH; ci++) {
        const int m0 = m0base + ci * 64;
        const int buf = ci & 1;

        // ---- L phase: build A fragments in registers ----
        uint32_t Ah[4][4], Al[4][4];
        {
            uint32_t m8A[8], m8B[8];
            #pragma unroll
            for (int g = 0; g < 8; g++) {
                m8A[g] = mks[buf * 1024 + g * 128 + rowA];
                m8B[g] = mks[buf * 1024 + g * 128 + rowB];
            }
            const float* w2b = w2s + buf * 256;

            #pragma unroll
            for (int kt = 0; kt < 4; kt++) {
                const int wsel = kt >> 1;
                #pragma unroll
                for (int p = 0; p < 2; p++) {
                    const int j = kt * 16 + c0j + p * 8;
                    const int bit = (kt & 1) * 16 + c0j + p * 8;
                    float svA0 = 0.f, svA1 = 0.f, svB0 = 0.f, svB1 = 0.f;
                    #pragma unroll
                    for (int k = 0; k < KNET; k++) {
                        const float2 w2v = *reinterpret_cast<const float2*>(w2b + k * 64 + j);
                        const uint32_t mwA = m8A[k * 2 + wsel];
                        const uint32_t mwB = m8B[k * 2 + wsel];
                        const float wk = wts[k];
                        float v, lr;
                        v = w1A[k] + w2v.x; lr = fmaxf(v, ALPHA * v);
                        svA0 += ((mwA >> bit) & 1u) ? wk * lr : 0.f;
                        v = w1A[k] + w2v.y; lr = fmaxf(v, ALPHA * v);
                        svA1 += ((mwA >> (bit + 1)) & 1u) ? wk * lr : 0.f;
                        v = w1B[k] + w2v.x; lr = fmaxf(v, ALPHA * v);
                        svB0 += ((mwB >> bit) & 1u) ? wk * lr : 0.f;
                        v = w1B[k] + w2v.y; lr = fmaxf(v, ALPHA * v);
                        svB1 += ((mwB >> (bit + 1)) & 1u) ? wk * lr : 0.f;
                    }
                    const float eA0 = fexp(svA0), eA1 = fexp(svA1);
                    const float eB0 = fexp(svB0), eB1 = fexp(svB1);
                    denA += eA0 + eA1;
                    denB += eB0 + eB1;
                    const float hA0 = __bfloat162float(__float2bfloat16(eA0));
                    const float hA1 = __bfloat162float(__float2bfloat16(eA1));
                    const float hB0 = __bfloat162float(__float2bfloat16(eB0));
                    const float hB1 = __bfloat162float(__float2bfloat16(eB1));
                    PACK_BF16X2(Ah[kt][p * 2 + 0], eA0, eA1);
                    PACK_BF16X2(Ah[kt][p * 2 + 1], eB0, eB1);
                    PACK_BF16X2(Al[kt][p * 2 + 0], eA0 - hA0, eA1 - hA1);
                    PACK_BF16X2(Al[kt][p * 2 + 1], eB0 - hB0, eB1 - hB1);
                }
            }
        }

        // stage next chunk into the other buffer (no conflict with this chunk)
        if (ci + 1 < CH) {
            stage_wh(buf ^ 1, m0 + 64);
            stage_w2(buf ^ 1, m0 + 64);
            stage_mk(buf ^ 1, m0 + 64);
        }

        // ---- M phase: mma.sync (B from smem, A from registers) ----
        {
            const uint32_t bbase = sb + SM_WH + buf * (2 * WH_TILE);
            const uint32_t boff = (uint32_t)(lane & 15) * (WHPITCH * 2)
                                + (uint32_t)(lane >> 4) * 16;
            #pragma unroll
            for (int np = 0; np < 8; np++) {
                #pragma unroll
                for (int kt = 0; kt < 4; kt++) {
                    const uint32_t addr = bbase + boff + kt * (16 * WHPITCH * 2) + np * 32;
                    uint32_t Bh[4], Bl[4];
                    ldsm_x4_t(Bh, addr);
                    ldsm_x4_t(Bl, addr + WH_TILE);
                    float* a0 = acc[np * 2];
                    float* a1 = acc[np * 2 + 1];
                    mma_bf16(a0, Ah[kt], Bh);
                    mma_bf16(a0, Ah[kt], Bl);
                    mma_bf16(a0, Al[kt], Bh);
                    mma_bf16(a1, Ah[kt], Bh + 2);
                    mma_bf16(a1, Ah[kt], Bl + 2);
                    mma_bf16(a1, Al[kt], Bh + 2);
                }
            }
        }
        __syncthreads();   // single barrier: staging(buf^1) done; M(buf) done
    }

    // denominators: reduce over the 4 lanes sharing each row
    {
        float dA = denA + __shfl_xor_sync(0xffffffffu, denA, 1);
        dA += __shfl_xor_sync(0xffffffffu, dA, 2);
        float dB = denB + __shfl_xor_sync(0xffffffffu, denB, 1);
        dB += __shfl_xor_sync(0xffffffffu, dB, 2);
        if ((lane & 3) == 0) {
            g_den[s * NN + n0 + rowA] = dA;
            g_den[s * NN + n0 + rowB] = dB;
        }
    }

    // partial numerators (D fragment layout of m16n8)
    {
        const int rA = r0w + (lane >> 2);
        const int cA = (lane & 3) * 2;
        #pragma unroll
        for (int nt = 0; nt < 16; nt++) {
            const int col = nt * 8 + cA;
            float* base = &g_part[((size_t)s * NN + n0 + rA) * OUT_D + col];
            *reinterpret_cast<float2*>(base) = make_float2(acc[nt][0], acc[nt][1]);
            *reinterpret_cast<float2*>(base + 8 * OUT_D) = make_float2(acc[nt][2], acc[nt][3]);
        }
    }
}

// ---------------------------------------------------------------------------
// Kernel 3: combine NSPLIT partials, normalize, ELU, store
// ---------------------------------------------------------------------------
__global__ void __launch_bounds__(256) finalize_kernel(float* __restrict__ out)
{
    const int idx = blockIdx.x * 256 + threadIdx.x;
    const int n = idx >> 5;
    const float4* P = reinterpret_cast<const float4*>(g_part);
    float4 p = P[idx];
    float den = g_den[n];
    #pragma unroll
    for (int s = 1; s < NSPLIT; s++) {
        float4 q = P[idx + (size_t)s * (NN * OUT_D / 4)];
        p.x += q.x; p.y += q.y; p.z += q.z; p.w += q.w;
        den += g_den[s * NN + n];
    }
    const float inv = 1.0f / den;
    float4 o; float x;
    x = p.x * inv; o.x = x > 0.f ? x : fexp(x) - 1.0f;
    x = p.y * inv; o.y = x > 0.f ? x : fexp(x) - 1.0f;
    x = p.z * inv; o.z = x > 0.f ? x : fexp(x) - 1.0f;
    x = p.w * inv; o.w = x > 0.f ? x : fexp(x) - 1.0f;
    reinterpret_cast<float4*>(out)[idx] = o;
}

// ---------------------------------------------------------------------------
// Stream fork (static-init host objects; deterministic sequence per call)
// ---------------------------------------------------------------------------
namespace {
struct AuxStream {
    cudaStream_t s = nullptr;
    cudaEvent_t  e0 = nullptr, e1 = nullptr;
    bool ok = false;
    AuxStream() {
        ok = (cudaStreamCreateWithFlags(&s, cudaStreamNonBlocking) == cudaSuccess)
          && (cudaEventCreateWithFlags(&e0, cudaEventDisableTiming) == cudaSuccess)
          && (cudaEventCreateWithFlags(&e1, cudaEventDisableTiming) == cudaSuccess);
    }
};
AuxStream g_aux;
}

// ---------------------------------------------------------------------------
extern "C" void kernel_launch(void* const* d_in, const int* in_sizes, int n_in,
                              void* d_out, int out_size)
{
    const float* h    = (const float*)d_in[0];   // [4096, 512]
    const int*   adjs = (const int*)  d_in[1];   // [4, 4096, 4096]
    const float* W    = (const float*)d_in[2];   // [512, 128]
    const float* a    = (const float*)d_in[3];   // [1024]
    const float* nw   = (const float*)d_in[4];   // [4]
    float* out = (float*)d_out;                  // [4096, 128]

    cudaFuncSetAttribute(attn_fused_kernel,
                         cudaFuncAttributeMaxDynamicSharedMemorySize, SMEM_TOTAL);

    if (g_aux.ok) {
        cudaEventRecord(g_aux.e0, 0);
        cudaStreamWaitEvent(g_aux.s, g_aux.e0, 0);
        wh_prep_kernel<<<NN / 16, 256>>>(h, W, a);          // enqueued first
        bitpack_kernel<<<2048, 256, 0, g_aux.s>>>(adjs);
        cudaEventRecord(g_aux.e1, g_aux.s);
        cudaStreamWaitEvent(0, g_aux.e1, 0);                // join before fused
    } else {
        bitpack_kernel<<<2048, 256>>>(adjs);
        wh_prep_kernel<<<NN / 16, 256>>>(h, W, a);
    }
    attn_fused_kernel<<<dim3(NN / 128, NSPLIT), 256, SMEM_TOTAL>>>(nw);
    finalize_kernel<<<NN * OUT_D / 4 / 256, 256>>>(out);
}